// round 15
// baseline (speedup 1.0000x reference)
#include <cuda_runtime.h>
#include <cuda_bf16.h>
#include <stdint.h>
#include <math.h>

#define N_NODES 50000
#define N_PAD   50048          // 391 * 128
#define N_EDGES 800000
#define N_REL 8
#define HID 128
#define OUT_CH 64
#define NBIN (N_NODES * N_REL) // 400000
#define SCAN_NB 391
#define LIN_NB 1564            // ceil(50000/32)

// ---------------- scratch ----------------
__device__ __align__(16) float g_h [N_NODES * HID];
__device__ __align__(16) float g_h2[N_NODES * HID];
__device__ __align__(128) __nv_bfloat16 g_Zbf[(size_t)N_PAD * 2048]; // hi 0..1023 | lo 1024..2047
__device__ __align__(16) __nv_bfloat16 g_Wbf[2][2048 * 128];        // per layer: hi rows 0..1023 | lo
__device__ __align__(16) float g_qw[2][N_REL * 128];
__device__ __align__(16) float g_kw[2][N_REL * 128];
__device__ float g_sq[N_NODES * N_REL];
__device__ float g_sk[N_NODES * N_REL];
__device__ int   g_srcs [N_EDGES];
__device__ int   g_deg8[NBIN];
__device__ int   g_cur8[NBIN];
__device__ int   g_off8[NBIN + 1];
__device__ int   g_bsum[SCAN_NB];
__device__ int   g_boff[SCAN_NB];

// ================= PTX helpers =================
__device__ __forceinline__ uint32_t smem_u32(const void* p) {
    uint32_t a;
    asm("{ .reg .u64 t; cvta.to.shared.u64 t, %1; cvt.u32.u64 %0, t; }" : "=r"(a) : "l"(p));
    return a;
}
#define CP16(dst, src) \
    asm volatile("cp.async.cg.shared.global [%0], [%1], 16;" :: "r"(dst), "l"(src))
#define CP_COMMIT() asm volatile("cp.async.commit_group;" ::: "memory")
#define CP_WAIT2()  asm volatile("cp.async.wait_group 2;" ::: "memory")

#define LDSM_X4(r, addr) \
    asm volatile("ldmatrix.sync.aligned.m8n8.x4.shared.b16 {%0,%1,%2,%3}, [%4];" \
        : "=r"((r)[0]), "=r"((r)[1]), "=r"((r)[2]), "=r"((r)[3]) : "r"(addr))
#define LDSM_X4_T(r0, r1, r2, r3, addr) \
    asm volatile("ldmatrix.sync.aligned.m8n8.x4.trans.shared.b16 {%0,%1,%2,%3}, [%4];" \
        : "=r"(r0), "=r"(r1), "=r"(r2), "=r"(r3) : "r"(addr))

#define MMA_BF16(d, a, b) \
    asm volatile("mma.sync.aligned.m16n8k16.row.col.f32.bf16.bf16.f32 " \
        "{%0,%1,%2,%3}, {%4,%5,%6,%7}, {%8,%9}, {%0,%1,%2,%3};" \
        : "+f"((d)[0]), "+f"((d)[1]), "+f"((d)[2]), "+f"((d)[3]) \
        : "r"((a)[0]), "r"((a)[1]), "r"((a)[2]), "r"((a)[3]), "r"((b)[0]), "r"((b)[1]))

__device__ __forceinline__ uint32_t sw128(uint32_t b) { return b ^ ((b >> 3) & 0x70); }

// GEMM tile (verified R7): M=128, N=128, BK=64, 3 stages, 256 threads
#define ST_ALO 16384
#define ST_BHI 32768
#define ST_BLO 50176
#define STAGE_BYTES 67584
#define GEMM_SMEM (3 * STAGE_BYTES)

// ---------------- prep0: register-blocked lin (smem-staged W^T) + zero bins ----------------
__global__ __launch_bounds__(256) void prep0_kernel(const float* __restrict__ z,
                                                    const float* __restrict__ W,
                                                    const float* __restrict__ b) {
    __shared__ float swt[64 * 128];    // W transposed [i][c], 32 KB
    if (blockIdx.x < LIN_NB) {
        int t = threadIdx.x;
        for (int s = t; s < 64 * 128; s += 256) {
            int c = s >> 6, i = s & 63;
            swt[i * 128 + c] = W[s];
        }
        __syncthreads();

        int cg = t & 31;            // cols cg*4 .. cg*4+3
        int ng = t >> 5;            // 0..7
        int nbase = blockIdx.x * 32 + ng * 4;
        float4 acc0 = make_float4(0.f, 0.f, 0.f, 0.f);
        float4 acc1 = acc0, acc2 = acc0, acc3 = acc0;
#pragma unroll
        for (int i4 = 0; i4 < 16; ++i4) {
            float4 w0 = *(const float4*)(swt + (i4 * 4 + 0) * 128 + cg * 4);
            float4 w1 = *(const float4*)(swt + (i4 * 4 + 1) * 128 + cg * 4);
            float4 w2 = *(const float4*)(swt + (i4 * 4 + 2) * 128 + cg * 4);
            float4 w3 = *(const float4*)(swt + (i4 * 4 + 3) * 128 + cg * 4);
#pragma unroll
            for (int j = 0; j < 4; ++j) {
                int n = nbase + j;
                float4 z4 = make_float4(0.f, 0.f, 0.f, 0.f);
                if (n < N_NODES) z4 = *(const float4*)(z + (size_t)n * OUT_CH + i4 * 4);
                float4* ac = (j == 0) ? &acc0 : (j == 1) ? &acc1 : (j == 2) ? &acc2 : &acc3;
                ac->x += z4.x * w0.x + z4.y * w1.x + z4.z * w2.x + z4.w * w3.x;
                ac->y += z4.x * w0.y + z4.y * w1.y + z4.z * w2.y + z4.w * w3.y;
                ac->z += z4.x * w0.z + z4.y * w1.z + z4.z * w2.z + z4.w * w3.z;
                ac->w += z4.x * w0.w + z4.y * w1.w + z4.z * w2.w + z4.w * w3.w;
            }
        }
        float4 bb = *(const float4*)(b + cg * 4);
#pragma unroll
        for (int j = 0; j < 4; ++j) {
            int n = nbase + j;
            if (n < N_NODES) {
                float4 a = (j == 0) ? acc0 : (j == 1) ? acc1 : (j == 2) ? acc2 : acc3;
                *(float4*)(g_h + (size_t)n * 128 + cg * 4) =
                    make_float4(a.x + bb.x, a.y + bb.y, a.z + bb.z, a.w + bb.w);
            }
        }
    } else {
        int i = (blockIdx.x - LIN_NB) * 256 + threadIdx.x;
        if (i < NBIN) { g_deg8[i] = 0; g_cur8[i] = 0; }
    }
}

// ---------------- CSR build ----------------
__global__ void hist8_kernel(const int* __restrict__ dst, const int* __restrict__ et) {
    int e = blockIdx.x * blockDim.x + threadIdx.x;
    if (e < N_EDGES) atomicAdd(&g_deg8[dst[e] * 8 + et[e]], 1);
}
__global__ __launch_bounds__(1024) void scan1_kernel() {
    __shared__ int sh[1024];
    int b = blockIdx.x, t = threadIdx.x;
    int i = b * 1024 + t;
    int v = (i < NBIN) ? g_deg8[i] : 0;
    sh[t] = v; __syncthreads();
#pragma unroll
    for (int d = 1; d < 1024; d <<= 1) {
        int x = (t >= d) ? sh[t - d] : 0;
        __syncthreads(); sh[t] += x; __syncthreads();
    }
    if (i < NBIN) g_off8[i] = sh[t] - v;
    if (t == 1023) g_bsum[b] = sh[1023];
}
__global__ __launch_bounds__(512) void scan2_kernel() {
    __shared__ int sh[512];
    int t = threadIdx.x;
    int v = (t < SCAN_NB) ? g_bsum[t] : 0;
    sh[t] = v; __syncthreads();
#pragma unroll
    for (int d = 1; d < 512; d <<= 1) {
        int x = (t >= d) ? sh[t - d] : 0;
        __syncthreads(); sh[t] += x; __syncthreads();
    }
    if (t < SCAN_NB) g_boff[t] = sh[t] - v;
    if (t == SCAN_NB - 1) g_off8[NBIN] = sh[t];
}
__global__ __launch_bounds__(1024) void scan3_kernel() {
    int i = blockIdx.x * 1024 + threadIdx.x;
    if (i < NBIN) g_off8[i] += g_boff[blockIdx.x];
}
__global__ void scatter_kernel(const int* __restrict__ src,
                               const int* __restrict__ dst,
                               const int* __restrict__ et) {
    int e = blockIdx.x * blockDim.x + threadIdx.x;
    if (e >= N_EDGES) return;
    int key = dst[e] * 8 + et[e];
    int pos = g_off8[key] + atomicAdd(&g_cur8[key], 1);
    g_srcs[pos] = src[e];
}

// ---------------- qk + splitW, BOTH layers in one launch ----------------
// blocks [0,16): L0 qk | [16,1040): L0 splitW | [1040,1056): L1 qk | [1056,2080): L1 splitW
__global__ __launch_bounds__(128) void qkW_kernel(const float* __restrict__ w1,
                                                  const float* __restrict__ q1,
                                                  const float* __restrict__ k1,
                                                  const float* __restrict__ w2,
                                                  const float* __restrict__ q2,
                                                  const float* __restrict__ k2) {
    int layer = (blockIdx.x >= 1040) ? 1 : 0;
    int local = blockIdx.x - layer * 1040;
    const float* w = layer ? w2 : w1;
    const float* q = layer ? q2 : q1;
    const float* k = layer ? k2 : k1;
    if (local < 16) {
        int r = local >> 1;
        int isK = local & 1;
        int i = threadIdx.x;
        const float4* wr = (const float4*)(w + (((size_t)r * 128 + i) << 7));
        const float4* v  = (const float4*)(isK ? k : q);
        float acc = 0.f;
#pragma unroll
        for (int o = 0; o < 32; ++o) {
            float4 a = wr[o], b = v[o];
            acc += a.x * b.x + a.y * b.y + a.z * b.z + a.w * b.w;
        }
        if (isK) g_kw[layer][r * 128 + i] = acc;
        else     g_qw[layer][r * 128 + i] = acc;
    } else {
        int t = (local - 16) * 128 + threadIdx.x;
        float x = w[t];
        __nv_bfloat16 hi = __float2bfloat16(x);
        __nv_bfloat16 lo = __float2bfloat16(x - __bfloat162float(hi));
        g_Wbf[layer][t] = hi;
        g_Wbf[layer][1024 * 128 + t] = lo;
    }
}

// ---------------- s: warp-per-node, butterfly 16-slot reduction ----------------
__global__ __launch_bounds__(256) void s_kernel(int layer) {
    const float* __restrict__ hin = (layer == 0) ? g_h : g_h2;
    __shared__ float sw[16][128];
    int tid = threadIdx.x;
#pragma unroll
    for (int i = 0; i < 8; ++i) {
        int idx = tid + i * 256;
        int rw = idx >> 7, k = idx & 127;
        sw[rw][k] = (rw & 1) ? g_kw[layer][(rw >> 1) * 128 + k]
                             : g_qw[layer][(rw >> 1) * 128 + k];
    }
    __syncthreads();

    int wid = tid >> 5, lane = tid & 31;
    int n = blockIdx.x * 8 + wid;
    if (n >= N_NODES) return;

    float4 h4 = *(const float4*)(hin + (size_t)n * 128 + lane * 4);
    float acc[16];
#pragma unroll
    for (int rw = 0; rw < 16; ++rw) {
        float4 w4 = *(const float4*)(&sw[rw][lane * 4]);
        acc[rw] = h4.x * w4.x + h4.y * w4.y + h4.z * w4.z + h4.w * w4.w;
    }
#pragma unroll
    for (int i = 0; i < 16; ++i) acc[i] += __shfl_xor_sync(0xffffffffu, acc[i], 16);
#pragma unroll
    for (int off = 8; off >= 1; off >>= 1) {
        bool up = (lane & off) != 0;
#pragma unroll
        for (int i = 0; i < 8; ++i) {
            if (i >= off) break;
            float send = up ? acc[i] : acc[i + off];
            float recv = __shfl_xor_sync(0xffffffffu, send, off);
            acc[i] = (up ? acc[i + off] : acc[i]) + recv;
        }
    }
    if (lane < 16) {
        int r = lane >> 1;
        if (lane & 1) g_sk[n * 8 + r] = acc[0];
        else          g_sq[n * 8 + r] = acc[0];
    }
}

// ---------------- warp-per-node: fused logits + softmax + aggregate -> Zbf ----------------
__device__ __forceinline__ void store_z(__nv_bfloat16* zr, int r, float4 v) {
    __nv_bfloat162 h01 = __float22bfloat162_rn(make_float2(v.x, v.y));
    __nv_bfloat162 h23 = __float22bfloat162_rn(make_float2(v.z, v.w));
    __nv_bfloat162 l01 = __float22bfloat162_rn(make_float2(v.x - __bfloat162float(h01.x),
                                                           v.y - __bfloat162float(h01.y)));
    __nv_bfloat162 l23 = __float22bfloat162_rn(make_float2(v.z - __bfloat162float(h23.x),
                                                           v.w - __bfloat162float(h23.y)));
    union { __nv_bfloat162 b2[2]; unsigned long long u; } H, L;
    H.b2[0] = h01; H.b2[1] = h23;
    L.b2[0] = l01; L.b2[1] = l23;
    __stcs((unsigned long long*)(zr + r * 128), H.u);
    __stcs((unsigned long long*)(zr + 1024 + r * 128), L.u);
}

__global__ __launch_bounds__(128) void aggregate_kernel(int layer) {
    const float* __restrict__ hin = (layer == 0) ? g_h : g_h2;
    int n = blockIdx.x * 4 + (threadIdx.x >> 5);
    if (n >= N_NODES) return;
    int lane = threadIdx.x & 31;
    int n8 = n * 8;
    const uint32_t FULL = 0xffffffffu;

    int offv = __ldg(&g_off8[n8 + min(lane, 8)]);
    int s = __shfl_sync(FULL, offv, 0);
    int e = __shfl_sync(FULL, offv, 8);
    int deg = e - s;

    const float* hbase = hin + lane * 4;
    __nv_bfloat16* zr = g_Zbf + (size_t)n * 2048 + lane * 4;

    if (deg <= 32) {
        bool has = lane < deg;
        int myj = s + lane;
        int snv = has ? __ldg(g_srcs + myj) : 0;
        int r_lane = 0;
#pragma unroll
        for (int rr = 1; rr <= 7; ++rr)
            r_lane += (myj >= __shfl_sync(FULL, offv, rr)) ? 1 : 0;
        float av = -1e30f;
        if (has) {
            float a = __ldg(g_sq + n8 + r_lane) + __ldg(g_sk + snv * 8 + r_lane);
            av = (a > 0.f) ? a : 0.2f * a;
        }
        float mx = av;
#pragma unroll
        for (int o = 16; o; o >>= 1) mx = fmaxf(mx, __shfl_xor_sync(FULL, mx, o));
        float ex = has ? __expf(av - mx) : 0.f;
        float den = ex;
#pragma unroll
        for (int o = 16; o; o >>= 1) den += __shfl_xor_sync(FULL, den, o);
        float inv = 1.f / (den + 1e-16f);

#pragma unroll
        for (int r = 0; r < 8; ++r) {
            int a = __shfl_sync(FULL, offv, r);
            int b = __shfl_sync(FULL, offv, r + 1);
            float4 acc = make_float4(0.f, 0.f, 0.f, 0.f);
            for (int j = a; j < b; ++j) {
                int idx = j - s;
                float w = __shfl_sync(FULL, ex, idx);
                int sn = __shfl_sync(FULL, snv, idx);
                float4 hv = *(const float4*)(hbase + (size_t)sn * 128);
                acc.x += w * hv.x; acc.y += w * hv.y;
                acc.z += w * hv.z; acc.w += w * hv.w;
            }
            store_z(zr, r, make_float4(acc.x * inv, acc.y * inv, acc.z * inv, acc.w * inv));
        }
    } else {
        int bnd[7];
#pragma unroll
        for (int rr = 1; rr <= 7; ++rr) bnd[rr - 1] = __shfl_sync(FULL, offv, rr);

        float mx = -1e30f;
        for (int j = s + lane; j < e; j += 32) {
            int r = 0;
#pragma unroll
            for (int i = 0; i < 7; ++i) r += (j >= bnd[i]) ? 1 : 0;
            int sn = __ldg(g_srcs + j);
            float a = __ldg(g_sq + n8 + r) + __ldg(g_sk + sn * 8 + r);
            a = (a > 0.f) ? a : 0.2f * a;
            mx = fmaxf(mx, a);
        }
#pragma unroll
        for (int o = 16; o; o >>= 1) mx = fmaxf(mx, __shfl_xor_sync(FULL, mx, o));
        float den = 0.f;
        for (int j = s + lane; j < e; j += 32) {
            int r = 0;
#pragma unroll
            for (int i = 0; i < 7; ++i) r += (j >= bnd[i]) ? 1 : 0;
            int sn = __ldg(g_srcs + j);
            float a = __ldg(g_sq + n8 + r) + __ldg(g_sk + sn * 8 + r);
            a = (a > 0.f) ? a : 0.2f * a;
            den += __expf(a - mx);
        }
#pragma unroll
        for (int o = 16; o; o >>= 1) den += __shfl_xor_sync(FULL, den, o);
        float inv = 1.f / (den + 1e-16f);

        int a0 = s;
#pragma unroll
        for (int r = 0; r < 8; ++r) {
            int b0 = __ldg(&g_off8[n8 + r + 1]);
            float sq_r = __ldg(g_sq + n8 + r);
            float4 acc = make_float4(0.f, 0.f, 0.f, 0.f);
            for (int j = a0; j < b0; ++j) {
                int sn = __ldg(g_srcs + j);
                float a = sq_r + __ldg(g_sk + sn * 8 + r);
                a = (a > 0.f) ? a : 0.2f * a;
                float w = __expf(a - mx);
                float4 hv = *(const float4*)(hbase + (size_t)sn * 128);
                acc.x += w * hv.x; acc.y += w * hv.y;
                acc.z += w * hv.z; acc.w += w * hv.w;
            }
            a0 = b0;
            store_z(zr, r, make_float4(acc.x * inv, acc.y * inv, acc.z * inv, acc.w * inv));
        }
    }
}

// ================= mma.sync bf16 GEMM (verified R7): 256 threads, M=128, N=128, 3-stage =================
__device__ __forceinline__ void stage_load(uint32_t st, int koff, int bm, int tid, int layer) {
#pragma unroll
    for (int it = 0; it < 4; ++it) {
        int i = tid + it * 256;
        int m = i >> 3, seg = i & 7;
        uint32_t sw = sw128((uint32_t)(m * 128 + seg * 16));
        const char* src = (const char*)(g_Zbf + (size_t)(bm + m) * 2048 + koff + seg * 8);
        CP16(st + sw, src);
        CP16(st + ST_ALO + sw, src + 2048);
    }
#pragma unroll
    for (int it = 0; it < 4; ++it) {
        int i = tid + it * 256;
        int k = i >> 4, nseg = i & 15;
        const char* src = (const char*)(g_Wbf[layer] + (size_t)(koff + k) * 128 + nseg * 8);
        CP16(st + ST_BHI + k * 272 + nseg * 16, src);
        CP16(st + ST_BLO + k * 272 + nseg * 16, src + 1024 * 128 * 2);
    }
}

__global__ __launch_bounds__(256, 1) void gemm_mma_kernel(float* __restrict__ out_ext,
                                                          const float* __restrict__ bias,
                                                          int relu, int to_h2, int layer) {
    extern __shared__ char sm[];
    uint32_t sb = smem_u32(sm);
    const int tid = threadIdx.x;
    const int wid = tid >> 5, lane = tid & 31;
    const int bm = blockIdx.x * 128;
    const int wm = wid & 3, wn = wid >> 2;

    float acc[2][8][4];
#pragma unroll
    for (int i = 0; i < 2; ++i)
#pragma unroll
        for (int j = 0; j < 8; ++j)
#pragma unroll
            for (int l = 0; l < 4; ++l) acc[i][j][l] = 0.f;

#pragma unroll
    for (int p = 0; p < 3; ++p) {
        stage_load(sb + p * STAGE_BYTES, p * 64, bm, tid, layer);
        CP_COMMIT();
    }

    const int rA = lane & 15, cA = lane >> 4;
    const int rB8 = (lane & 7) + ((lane >> 3) & 1) * 8;
    const int nB = wn * 64 + (lane >> 4) * 8;

    for (int c = 0; c < 16; ++c) {
        CP_WAIT2();
        __syncthreads();
        uint32_t st = sb + (uint32_t)(c % 3) * STAGE_BYTES;

#pragma unroll
        for (int k16 = 0; k16 < 4; ++k16) {
            uint32_t aHi[2][4], aLo[2][4], bHi[8][2], bLo[8][2];
#pragma unroll
            for (int mt = 0; mt < 2; ++mt) {
                uint32_t sw = sw128((uint32_t)((wm * 32 + mt * 16 + rA) * 128 + k16 * 32 + cA * 16));
                LDSM_X4(aHi[mt], st + sw);
                LDSM_X4(aLo[mt], st + ST_ALO + sw);
            }
#pragma unroll
            for (int p = 0; p < 4; ++p) {
                uint32_t boff = (uint32_t)((k16 * 16 + rB8) * 272 + (nB + p * 16) * 2);
                LDSM_X4_T(bHi[2 * p][0], bHi[2 * p][1], bHi[2 * p + 1][0], bHi[2 * p + 1][1],
                          st + ST_BHI + boff);
                LDSM_X4_T(bLo[2 * p][0], bLo[2 * p][1], bLo[2 * p + 1][0], bLo[2 * p + 1][1],
                          st + ST_BLO + boff);
            }
#pragma unroll
            for (int mt = 0; mt < 2; ++mt)
#pragma unroll
                for (int nt = 0; nt < 8; ++nt) MMA_BF16(acc[mt][nt], aHi[mt], bHi[nt]);
#pragma unroll
            for (int mt = 0; mt < 2; ++mt)
#pragma unroll
                for (int nt = 0; nt < 8; ++nt) MMA_BF16(acc[mt][nt], aLo[mt], bHi[nt]);
#pragma unroll
            for (int mt = 0; mt < 2; ++mt)
#pragma unroll
                for (int nt = 0; nt < 8; ++nt) MMA_BF16(acc[mt][nt], aHi[mt], bLo[nt]);
        }
        __syncthreads();
        if (c + 3 < 16) stage_load(st, (c + 3) * 64, bm, tid, layer);
        CP_COMMIT();
    }

    float* __restrict__ outp = to_h2 ? g_h2 : out_ext;
    const int g = lane >> 2, t4 = lane & 3;
#pragma unroll
    for (int mt = 0; mt < 2; ++mt) {
        int row0 = bm + wm * 32 + mt * 16 + g;
        int row1 = row0 + 8;
#pragma unroll
        for (int nt = 0; nt < 8; ++nt) {
            int col = wn * 64 + nt * 8 + t4 * 2;
            float b0 = __ldg(bias + col), b1 = __ldg(bias + col + 1);
            float v00 = acc[mt][nt][0] + b0, v01 = acc[mt][nt][1] + b1;
            float v10 = acc[mt][nt][2] + b0, v11 = acc[mt][nt][3] + b1;
            if (relu) {
                v00 = fmaxf(v00, 0.f); v01 = fmaxf(v01, 0.f);
                v10 = fmaxf(v10, 0.f); v11 = fmaxf(v11, 0.f);
            }
            if (row0 < N_NODES) *(float2*)(outp + (size_t)row0 * 128 + col) = make_float2(v00, v01);
            if (row1 < N_NODES) *(float2*)(outp + (size_t)row1 * 128 + col) = make_float2(v10, v11);
        }
    }
}

// ---------------- launch ----------------
extern "C" void kernel_launch(void* const* d_in, const int* in_sizes, int n_in,
                              void* d_out, int out_size) {
    const float* z     = (const float*)d_in[0];
    const float* lin_w = (const float*)d_in[1];
    const float* lin_b = (const float*)d_in[2];
    const float* w1    = (const float*)d_in[3];
    const float* q1    = (const float*)d_in[4];
    const float* k1    = (const float*)d_in[5];
    const float* b1    = (const float*)d_in[6];
    const float* w2    = (const float*)d_in[7];
    const float* q2    = (const float*)d_in[8];
    const float* k2    = (const float*)d_in[9];
    const float* b2    = (const float*)d_in[10];
    const int*   ei    = (const int*)d_in[11];
    const int*   et    = (const int*)d_in[12];
    const int* src = ei;
    const int* dst = ei + N_EDGES;
    float* out = (float*)d_out;

    cudaFuncSetAttribute(gemm_mma_kernel, cudaFuncAttributeMaxDynamicSharedMemorySize, GEMM_SMEM);

    const int EB = N_EDGES / 256;      // 3125
    const int SB = (N_NODES + 7) / 8;  // 6250

    prep0_kernel<<<LIN_NB + 1563, 256>>>(z, lin_w, lin_b);
    qkW_kernel<<<2080, 128>>>(w1, q1, k1, w2, q2, k2);    // both layers
    hist8_kernel<<<EB, 256>>>(dst, et);
    s_kernel<<<SB, 256>>>(0);
    scan1_kernel<<<SCAN_NB, 1024>>>();
    scan2_kernel<<<1, 512>>>();
    scan3_kernel<<<SCAN_NB, 1024>>>();
    scatter_kernel<<<EB, 256>>>(src, dst, et);

    // ---- layer 1 ----
    aggregate_kernel<<<(N_NODES + 3) / 4, 128>>>(0);
    gemm_mma_kernel<<<N_PAD / 128, 256, GEMM_SMEM>>>(out, b1, 1, 1, 0);   // -> g_h2 (relu)

    // ---- layer 2 ----
    s_kernel<<<SB, 256>>>(1);
    aggregate_kernel<<<(N_NODES + 3) / 4, 128>>>(1);
    gemm_mma_kernel<<<N_PAD / 128, 256, GEMM_SMEM>>>(out, b2, 0, 0, 1);   // -> d_out
}

// round 16
// speedup vs baseline: 1.0806x; 1.0806x over previous
#include <cuda_runtime.h>
#include <cuda_bf16.h>
#include <stdint.h>
#include <math.h>

#define N_NODES 50000
#define N_PAD   50048          // 391 * 128
#define N_EDGES 800000
#define N_REL 8
#define HID 128
#define OUT_CH 64
#define NBIN (N_NODES * N_REL) // 400000
#define SCAN_NB 391
#define LIN_NB 1564            // ceil(50000/32)

// ---------------- scratch ----------------
__device__ __align__(16) float g_h [N_NODES * HID];
__device__ __align__(16) float g_h2[N_NODES * HID];
__device__ __align__(128) __nv_bfloat16 g_Zbf[(size_t)N_PAD * 2048]; // hi 0..1023 | lo 1024..2047
__device__ __align__(16) __nv_bfloat16 g_Wbf[2][2048 * 128];        // per layer: hi rows | lo rows
__device__ __align__(16) float g_qw[2][N_REL * 128];
__device__ __align__(16) float g_kw[2][N_REL * 128];
__device__ __align__(16) float g_Wt[64 * 128];      // lin_w transposed [i][c]
__device__ float g_sq[N_NODES * N_REL];
__device__ float g_sk[N_NODES * N_REL];
__device__ int   g_srcs [N_EDGES];
__device__ int   g_deg8[NBIN];
__device__ int   g_cur8[NBIN];
__device__ int   g_off8[NBIN + 1];
__device__ int   g_bsum[SCAN_NB];
__device__ int   g_boff[SCAN_NB];

// ================= PTX helpers =================
__device__ __forceinline__ uint32_t smem_u32(const void* p) {
    uint32_t a;
    asm("{ .reg .u64 t; cvta.to.shared.u64 t, %1; cvt.u32.u64 %0, t; }" : "=r"(a) : "l"(p));
    return a;
}
#define CP16(dst, src) \
    asm volatile("cp.async.cg.shared.global [%0], [%1], 16;" :: "r"(dst), "l"(src))
#define CP_COMMIT() asm volatile("cp.async.commit_group;" ::: "memory")
#define CP_WAIT2()  asm volatile("cp.async.wait_group 2;" ::: "memory")

#define LDSM_X4(r, addr) \
    asm volatile("ldmatrix.sync.aligned.m8n8.x4.shared.b16 {%0,%1,%2,%3}, [%4];" \
        : "=r"((r)[0]), "=r"((r)[1]), "=r"((r)[2]), "=r"((r)[3]) : "r"(addr))
#define LDSM_X4_T(r0, r1, r2, r3, addr) \
    asm volatile("ldmatrix.sync.aligned.m8n8.x4.trans.shared.b16 {%0,%1,%2,%3}, [%4];" \
        : "=r"(r0), "=r"(r1), "=r"(r2), "=r"(r3) : "r"(addr))

#define MMA_BF16(d, a, b) \
    asm volatile("mma.sync.aligned.m16n8k16.row.col.f32.bf16.bf16.f32 " \
        "{%0,%1,%2,%3}, {%4,%5,%6,%7}, {%8,%9}, {%0,%1,%2,%3};" \
        : "+f"((d)[0]), "+f"((d)[1]), "+f"((d)[2]), "+f"((d)[3]) \
        : "r"((a)[0]), "r"((a)[1]), "r"((a)[2]), "r"((a)[3]), "r"((b)[0]), "r"((b)[1]))

__device__ __forceinline__ uint32_t sw128(uint32_t b) { return b ^ ((b >> 3) & 0x70); }

// GEMM tile (verified R7): M=128, N=128, BK=64, 3 stages, 256 threads
#define ST_ALO 16384
#define ST_BHI 32768
#define ST_BLO 50176
#define STAGE_BYTES 67584
#define GEMM_SMEM (3 * STAGE_BYTES)

// ---------------- Wt transpose (tiny, runs first; verified R14) ----------------
__global__ void wt_kernel(const float* __restrict__ W) {
    for (int s = threadIdx.x; s < 64 * 128; s += 256) {
        int c = s >> 6, i = s & 63;
        g_Wt[i * 128 + c] = W[s];
    }
}

// ---------------- prep0: register-blocked lin + zero bins (verified R14) ----------------
__global__ __launch_bounds__(256) void prep0_kernel(const float* __restrict__ z,
                                                    const float* __restrict__ b) {
    if (blockIdx.x < LIN_NB) {
        int t = threadIdx.x;
        int cg = t & 31;            // cols cg*4 .. cg*4+3
        int ng = t >> 5;            // 0..7
        int nbase = blockIdx.x * 32 + ng * 4;
        float4 acc0 = make_float4(0.f, 0.f, 0.f, 0.f);
        float4 acc1 = acc0, acc2 = acc0, acc3 = acc0;
#pragma unroll
        for (int i4 = 0; i4 < 16; ++i4) {
            float4 w0 = *(const float4*)(g_Wt + (i4 * 4 + 0) * 128 + cg * 4);
            float4 w1 = *(const float4*)(g_Wt + (i4 * 4 + 1) * 128 + cg * 4);
            float4 w2 = *(const float4*)(g_Wt + (i4 * 4 + 2) * 128 + cg * 4);
            float4 w3 = *(const float4*)(g_Wt + (i4 * 4 + 3) * 128 + cg * 4);
#pragma unroll
            for (int j = 0; j < 4; ++j) {
                int n = nbase + j;
                float4 z4 = make_float4(0.f, 0.f, 0.f, 0.f);
                if (n < N_NODES) z4 = *(const float4*)(z + (size_t)n * OUT_CH + i4 * 4);
                float4* ac = (j == 0) ? &acc0 : (j == 1) ? &acc1 : (j == 2) ? &acc2 : &acc3;
                ac->x += z4.x * w0.x + z4.y * w1.x + z4.z * w2.x + z4.w * w3.x;
                ac->y += z4.x * w0.y + z4.y * w1.y + z4.z * w2.y + z4.w * w3.y;
                ac->z += z4.x * w0.z + z4.y * w1.z + z4.z * w2.z + z4.w * w3.z;
                ac->w += z4.x * w0.w + z4.y * w1.w + z4.z * w2.w + z4.w * w3.w;
            }
        }
        float4 bb = *(const float4*)(b + cg * 4);
#pragma unroll
        for (int j = 0; j < 4; ++j) {
            int n = nbase + j;
            if (n < N_NODES) {
                float4 a = (j == 0) ? acc0 : (j == 1) ? acc1 : (j == 2) ? acc2 : acc3;
                *(float4*)(g_h + (size_t)n * 128 + cg * 4) =
                    make_float4(a.x + bb.x, a.y + bb.y, a.z + bb.z, a.w + bb.w);
            }
        }
    } else {
        int i = (blockIdx.x - LIN_NB) * 256 + threadIdx.x;
        if (i < NBIN) { g_deg8[i] = 0; g_cur8[i] = 0; }
    }
}

// ---------------- CSR build ----------------
__global__ void hist8_kernel(const int* __restrict__ dst, const int* __restrict__ et) {
    int e = blockIdx.x * blockDim.x + threadIdx.x;
    if (e < N_EDGES) atomicAdd(&g_deg8[dst[e] * 8 + et[e]], 1);
}
__global__ __launch_bounds__(1024) void scan1_kernel() {
    __shared__ int sh[1024];
    int b = blockIdx.x, t = threadIdx.x;
    int i = b * 1024 + t;
    int v = (i < NBIN) ? g_deg8[i] : 0;
    sh[t] = v; __syncthreads();
#pragma unroll
    for (int d = 1; d < 1024; d <<= 1) {
        int x = (t >= d) ? sh[t - d] : 0;
        __syncthreads(); sh[t] += x; __syncthreads();
    }
    if (i < NBIN) g_off8[i] = sh[t] - v;
    if (t == 1023) g_bsum[b] = sh[1023];
}
__global__ __launch_bounds__(512) void scan2_kernel() {
    __shared__ int sh[512];
    int t = threadIdx.x;
    int v = (t < SCAN_NB) ? g_bsum[t] : 0;
    sh[t] = v; __syncthreads();
#pragma unroll
    for (int d = 1; d < 512; d <<= 1) {
        int x = (t >= d) ? sh[t - d] : 0;
        __syncthreads(); sh[t] += x; __syncthreads();
    }
    if (t < SCAN_NB) g_boff[t] = sh[t] - v;
    if (t == SCAN_NB - 1) g_off8[NBIN] = sh[t];
}
__global__ __launch_bounds__(1024) void scan3_kernel() {
    int i = blockIdx.x * 1024 + threadIdx.x;
    if (i < NBIN) g_off8[i] += g_boff[blockIdx.x];
}
__global__ void scatter_kernel(const int* __restrict__ src,
                               const int* __restrict__ dst,
                               const int* __restrict__ et) {
    int e = blockIdx.x * blockDim.x + threadIdx.x;
    if (e >= N_EDGES) return;
    int key = dst[e] * 8 + et[e];
    int pos = g_off8[key] + atomicAdd(&g_cur8[key], 1);
    g_srcs[pos] = src[e];
}

// ---------------- qk + splitW, BOTH layers in one launch ----------------
// blocks [0,16): L0 qk | [16,1040): L0 splitW | [1040,1056): L1 qk | [1056,2080): L1 splitW
__global__ __launch_bounds__(128) void qkW_kernel(const float* __restrict__ w1,
                                                  const float* __restrict__ q1,
                                                  const float* __restrict__ k1,
                                                  const float* __restrict__ w2,
                                                  const float* __restrict__ q2,
                                                  const float* __restrict__ k2) {
    int layer = (blockIdx.x >= 1040) ? 1 : 0;
    int local = blockIdx.x - layer * 1040;
    const float* w = layer ? w2 : w1;
    const float* q = layer ? q2 : q1;
    const float* k = layer ? k2 : k1;
    if (local < 16) {
        int r = local >> 1;
        int isK = local & 1;
        int i = threadIdx.x;
        const float4* wr = (const float4*)(w + (((size_t)r * 128 + i) << 7));
        const float4* v  = (const float4*)(isK ? k : q);
        float acc = 0.f;
#pragma unroll
        for (int o = 0; o < 32; ++o) {
            float4 a = wr[o], b = v[o];
            acc += a.x * b.x + a.y * b.y + a.z * b.z + a.w * b.w;
        }
        if (isK) g_kw[layer][r * 128 + i] = acc;
        else     g_qw[layer][r * 128 + i] = acc;
    } else {
        int t = (local - 16) * 128 + threadIdx.x;
        float x = w[t];
        __nv_bfloat16 hi = __float2bfloat16(x);
        __nv_bfloat16 lo = __float2bfloat16(x - __bfloat162float(hi));
        g_Wbf[layer][t] = hi;
        g_Wbf[layer][1024 * 128 + t] = lo;
    }
}

// ---------------- s: warp-per-node, butterfly 16-slot reduction ----------------
__global__ __launch_bounds__(256) void s_kernel(int layer) {
    const float* __restrict__ hin = (layer == 0) ? g_h : g_h2;
    __shared__ float sw[16][128];
    int tid = threadIdx.x;
#pragma unroll
    for (int i = 0; i < 8; ++i) {
        int idx = tid + i * 256;
        int rw = idx >> 7, k = idx & 127;
        sw[rw][k] = (rw & 1) ? g_kw[layer][(rw >> 1) * 128 + k]
                             : g_qw[layer][(rw >> 1) * 128 + k];
    }
    __syncthreads();

    int wid = tid >> 5, lane = tid & 31;
    int n = blockIdx.x * 8 + wid;
    if (n >= N_NODES) return;

    float4 h4 = *(const float4*)(hin + (size_t)n * 128 + lane * 4);
    float acc[16];
#pragma unroll
    for (int rw = 0; rw < 16; ++rw) {
        float4 w4 = *(const float4*)(&sw[rw][lane * 4]);
        acc[rw] = h4.x * w4.x + h4.y * w4.y + h4.z * w4.z + h4.w * w4.w;
    }
#pragma unroll
    for (int i = 0; i < 16; ++i) acc[i] += __shfl_xor_sync(0xffffffffu, acc[i], 16);
#pragma unroll
    for (int off = 8; off >= 1; off >>= 1) {
        bool up = (lane & off) != 0;
#pragma unroll
        for (int i = 0; i < 8; ++i) {
            if (i >= off) break;
            float send = up ? acc[i] : acc[i + off];
            float recv = __shfl_xor_sync(0xffffffffu, send, off);
            acc[i] = (up ? acc[i + off] : acc[i]) + recv;
        }
    }
    if (lane < 16) {
        int r = lane >> 1;
        if (lane & 1) g_sk[n * 8 + r] = acc[0];
        else          g_sq[n * 8 + r] = acc[0];
    }
}

// ---------------- warp-per-node: fused logits + softmax + aggregate -> Zbf ----------------
__device__ __forceinline__ void store_z(__nv_bfloat16* zr, int r, float4 v) {
    __nv_bfloat162 h01 = __float22bfloat162_rn(make_float2(v.x, v.y));
    __nv_bfloat162 h23 = __float22bfloat162_rn(make_float2(v.z, v.w));
    __nv_bfloat162 l01 = __float22bfloat162_rn(make_float2(v.x - __bfloat162float(h01.x),
                                                           v.y - __bfloat162float(h01.y)));
    __nv_bfloat162 l23 = __float22bfloat162_rn(make_float2(v.z - __bfloat162float(h23.x),
                                                           v.w - __bfloat162float(h23.y)));
    union { __nv_bfloat162 b2[2]; unsigned long long u; } H, L;
    H.b2[0] = h01; H.b2[1] = h23;
    L.b2[0] = l01; L.b2[1] = l23;
    __stcs((unsigned long long*)(zr + r * 128), H.u);
    __stcs((unsigned long long*)(zr + 1024 + r * 128), L.u);
}

__global__ __launch_bounds__(128) void aggregate_kernel(int layer) {
    const float* __restrict__ hin = (layer == 0) ? g_h : g_h2;
    int n = blockIdx.x * 4 + (threadIdx.x >> 5);
    if (n >= N_NODES) return;
    int lane = threadIdx.x & 31;
    int n8 = n * 8;
    const uint32_t FULL = 0xffffffffu;

    int offv = __ldg(&g_off8[n8 + min(lane, 8)]);
    int s = __shfl_sync(FULL, offv, 0);
    int e = __shfl_sync(FULL, offv, 8);
    int deg = e - s;

    const float* hbase = hin + lane * 4;
    __nv_bfloat16* zr = g_Zbf + (size_t)n * 2048 + lane * 4;

    if (deg <= 32) {
        bool has = lane < deg;
        int myj = s + lane;
        int snv = has ? __ldg(g_srcs + myj) : 0;
        int r_lane = 0;
#pragma unroll
        for (int rr = 1; rr <= 7; ++rr)
            r_lane += (myj >= __shfl_sync(FULL, offv, rr)) ? 1 : 0;
        float av = -1e30f;
        if (has) {
            float a = __ldg(g_sq + n8 + r_lane) + __ldg(g_sk + snv * 8 + r_lane);
            av = (a > 0.f) ? a : 0.2f * a;
        }
        float mx = av;
#pragma unroll
        for (int o = 16; o; o >>= 1) mx = fmaxf(mx, __shfl_xor_sync(FULL, mx, o));
        float ex = has ? __expf(av - mx) : 0.f;
        float den = ex;
#pragma unroll
        for (int o = 16; o; o >>= 1) den += __shfl_xor_sync(FULL, den, o);
        float inv = 1.f / (den + 1e-16f);

#pragma unroll
        for (int r = 0; r < 8; ++r) {
            int a = __shfl_sync(FULL, offv, r);
            int b = __shfl_sync(FULL, offv, r + 1);
            float4 acc = make_float4(0.f, 0.f, 0.f, 0.f);
            for (int j = a; j < b; ++j) {
                int idx = j - s;
                float w = __shfl_sync(FULL, ex, idx);
                int sn = __shfl_sync(FULL, snv, idx);
                float4 hv = *(const float4*)(hbase + (size_t)sn * 128);
                acc.x += w * hv.x; acc.y += w * hv.y;
                acc.z += w * hv.z; acc.w += w * hv.w;
            }
            store_z(zr, r, make_float4(acc.x * inv, acc.y * inv, acc.z * inv, acc.w * inv));
        }
    } else {
        int bnd[7];
#pragma unroll
        for (int rr = 1; rr <= 7; ++rr) bnd[rr - 1] = __shfl_sync(FULL, offv, rr);

        float mx = -1e30f;
        for (int j = s + lane; j < e; j += 32) {
            int r = 0;
#pragma unroll
            for (int i = 0; i < 7; ++i) r += (j >= bnd[i]) ? 1 : 0;
            int sn = __ldg(g_srcs + j);
            float a = __ldg(g_sq + n8 + r) + __ldg(g_sk + sn * 8 + r);
            a = (a > 0.f) ? a : 0.2f * a;
            mx = fmaxf(mx, a);
        }
#pragma unroll
        for (int o = 16; o; o >>= 1) mx = fmaxf(mx, __shfl_xor_sync(FULL, mx, o));
        float den = 0.f;
        for (int j = s + lane; j < e; j += 32) {
            int r = 0;
#pragma unroll
            for (int i = 0; i < 7; ++i) r += (j >= bnd[i]) ? 1 : 0;
            int sn = __ldg(g_srcs + j);
            float a = __ldg(g_sq + n8 + r) + __ldg(g_sk + sn * 8 + r);
            a = (a > 0.f) ? a : 0.2f * a;
            den += __expf(a - mx);
        }
#pragma unroll
        for (int o = 16; o; o >>= 1) den += __shfl_xor_sync(FULL, den, o);
        float inv = 1.f / (den + 1e-16f);

        int a0 = s;
#pragma unroll
        for (int r = 0; r < 8; ++r) {
            int b0 = __ldg(&g_off8[n8 + r + 1]);
            float sq_r = __ldg(g_sq + n8 + r);
            float4 acc = make_float4(0.f, 0.f, 0.f, 0.f);
            for (int j = a0; j < b0; ++j) {
                int sn = __ldg(g_srcs + j);
                float a = sq_r + __ldg(g_sk + sn * 8 + r);
                a = (a > 0.f) ? a : 0.2f * a;
                float w = __expf(a - mx);
                float4 hv = *(const float4*)(hbase + (size_t)sn * 128);
                acc.x += w * hv.x; acc.y += w * hv.y;
                acc.z += w * hv.z; acc.w += w * hv.w;
            }
            a0 = b0;
            store_z(zr, r, make_float4(acc.x * inv, acc.y * inv, acc.z * inv, acc.w * inv));
        }
    }
}

// ================= mma.sync bf16 GEMM (verified R7): 256 threads, M=128, N=128, 3-stage =================
__device__ __forceinline__ void stage_load(uint32_t st, int koff, int bm, int tid, int layer) {
#pragma unroll
    for (int it = 0; it < 4; ++it) {
        int i = tid + it * 256;
        int m = i >> 3, seg = i & 7;
        uint32_t sw = sw128((uint32_t)(m * 128 + seg * 16));
        const char* src = (const char*)(g_Zbf + (size_t)(bm + m) * 2048 + koff + seg * 8);
        CP16(st + sw, src);
        CP16(st + ST_ALO + sw, src + 2048);
    }
#pragma unroll
    for (int it = 0; it < 4; ++it) {
        int i = tid + it * 256;
        int k = i >> 4, nseg = i & 15;
        const char* src = (const char*)(g_Wbf[layer] + (size_t)(koff + k) * 128 + nseg * 8);
        CP16(st + ST_BHI + k * 272 + nseg * 16, src);
        CP16(st + ST_BLO + k * 272 + nseg * 16, src + 1024 * 128 * 2);
    }
}

__global__ __launch_bounds__(256, 1) void gemm_mma_kernel(float* __restrict__ out_ext,
                                                          const float* __restrict__ bias,
                                                          int relu, int to_h2, int layer) {
    extern __shared__ char sm[];
    uint32_t sb = smem_u32(sm);
    const int tid = threadIdx.x;
    const int wid = tid >> 5, lane = tid & 31;
    const int bm = blockIdx.x * 128;
    const int wm = wid & 3, wn = wid >> 2;

    float acc[2][8][4];
#pragma unroll
    for (int i = 0; i < 2; ++i)
#pragma unroll
        for (int j = 0; j < 8; ++j)
#pragma unroll
            for (int l = 0; l < 4; ++l) acc[i][j][l] = 0.f;

#pragma unroll
    for (int p = 0; p < 3; ++p) {
        stage_load(sb + p * STAGE_BYTES, p * 64, bm, tid, layer);
        CP_COMMIT();
    }

    const int rA = lane & 15, cA = lane >> 4;
    const int rB8 = (lane & 7) + ((lane >> 3) & 1) * 8;
    const int nB = wn * 64 + (lane >> 4) * 8;

    for (int c = 0; c < 16; ++c) {
        CP_WAIT2();
        __syncthreads();
        uint32_t st = sb + (uint32_t)(c % 3) * STAGE_BYTES;

#pragma unroll
        for (int k16 = 0; k16 < 4; ++k16) {
            uint32_t aHi[2][4], aLo[2][4], bHi[8][2], bLo[8][2];
#pragma unroll
            for (int mt = 0; mt < 2; ++mt) {
                uint32_t sw = sw128((uint32_t)((wm * 32 + mt * 16 + rA) * 128 + k16 * 32 + cA * 16));
                LDSM_X4(aHi[mt], st + sw);
                LDSM_X4(aLo[mt], st + ST_ALO + sw);
            }
#pragma unroll
            for (int p = 0; p < 4; ++p) {
                uint32_t boff = (uint32_t)((k16 * 16 + rB8) * 272 + (nB + p * 16) * 2);
                LDSM_X4_T(bHi[2 * p][0], bHi[2 * p][1], bHi[2 * p + 1][0], bHi[2 * p + 1][1],
                          st + ST_BHI + boff);
                LDSM_X4_T(bLo[2 * p][0], bLo[2 * p][1], bLo[2 * p + 1][0], bLo[2 * p + 1][1],
                          st + ST_BLO + boff);
            }
#pragma unroll
            for (int mt = 0; mt < 2; ++mt)
#pragma unroll
                for (int nt = 0; nt < 8; ++nt) MMA_BF16(acc[mt][nt], aHi[mt], bHi[nt]);
#pragma unroll
            for (int mt = 0; mt < 2; ++mt)
#pragma unroll
                for (int nt = 0; nt < 8; ++nt) MMA_BF16(acc[mt][nt], aLo[mt], bHi[nt]);
#pragma unroll
            for (int mt = 0; mt < 2; ++mt)
#pragma unroll
                for (int nt = 0; nt < 8; ++nt) MMA_BF16(acc[mt][nt], aHi[mt], bLo[nt]);
        }
        __syncthreads();
        if (c + 3 < 16) stage_load(st, (c + 3) * 64, bm, tid, layer);
        CP_COMMIT();
    }

    float* __restrict__ outp = to_h2 ? g_h2 : out_ext;
    const int g = lane >> 2, t4 = lane & 3;
#pragma unroll
    for (int mt = 0; mt < 2; ++mt) {
        int row0 = bm + wm * 32 + mt * 16 + g;
        int row1 = row0 + 8;
#pragma unroll
        for (int nt = 0; nt < 8; ++nt) {
            int col = wn * 64 + nt * 8 + t4 * 2;
            float b0 = __ldg(bias + col), b1 = __ldg(bias + col + 1);
            float v00 = acc[mt][nt][0] + b0, v01 = acc[mt][nt][1] + b1;
            float v10 = acc[mt][nt][2] + b0, v11 = acc[mt][nt][3] + b1;
            if (relu) {
                v00 = fmaxf(v00, 0.f); v01 = fmaxf(v01, 0.f);
                v10 = fmaxf(v10, 0.f); v11 = fmaxf(v11, 0.f);
            }
            if (row0 < N_NODES) *(float2*)(outp + (size_t)row0 * 128 + col) = make_float2(v00, v01);
            if (row1 < N_NODES) *(float2*)(outp + (size_t)row1 * 128 + col) = make_float2(v10, v11);
        }
    }
}

// ---------------- launch ----------------
extern "C" void kernel_launch(void* const* d_in, const int* in_sizes, int n_in,
                              void* d_out, int out_size) {
    const float* z     = (const float*)d_in[0];
    const float* lin_w = (const float*)d_in[1];
    const float* lin_b = (const float*)d_in[2];
    const float* w1    = (const float*)d_in[3];
    const float* q1    = (const float*)d_in[4];
    const float* k1    = (const float*)d_in[5];
    const float* b1    = (const float*)d_in[6];
    const float* w2    = (const float*)d_in[7];
    const float* q2    = (const float*)d_in[8];
    const float* k2    = (const float*)d_in[9];
    const float* b2    = (const float*)d_in[10];
    const int*   ei    = (const int*)d_in[11];
    const int*   et    = (const int*)d_in[12];
    const int* src = ei;
    const int* dst = ei + N_EDGES;
    float* out = (float*)d_out;

    cudaFuncSetAttribute(gemm_mma_kernel, cudaFuncAttributeMaxDynamicSharedMemorySize, GEMM_SMEM);

    const int EB = N_EDGES / 256;      // 3125
    const int SB = (N_NODES + 7) / 8;  // 6250

    wt_kernel<<<1, 256>>>(lin_w);
    prep0_kernel<<<LIN_NB + 1563, 256>>>(z, lin_b);
    qkW_kernel<<<2080, 128>>>(w1, q1, k1, w2, q2, k2);    // both layers
    hist8_kernel<<<EB, 256>>>(dst, et);
    s_kernel<<<SB, 256>>>(0);
    scan1_kernel<<<SCAN_NB, 1024>>>();
    scan2_kernel<<<1, 512>>>();
    scan3_kernel<<<SCAN_NB, 1024>>>();
    scatter_kernel<<<EB, 256>>>(src, dst, et);

    // ---- layer 1 ----
    aggregate_kernel<<<(N_NODES + 3) / 4, 128>>>(0);
    gemm_mma_kernel<<<N_PAD / 128, 256, GEMM_SMEM>>>(out, b1, 1, 1, 0);   // -> g_h2 (relu)

    // ---- layer 2 ----
    s_kernel<<<SB, 256>>>(1);
    aggregate_kernel<<<(N_NODES + 3) / 4, 128>>>(1);
    gemm_mma_kernel<<<N_PAD / 128, 256, GEMM_SMEM>>>(out, b2, 0, 0, 1);   // -> d_out
}